// round 9
// baseline (speedup 1.0000x reference)
#include <cuda_runtime.h>
#include <math.h>

#define FULL 0xffffffffu

// ---------------- problem constants ----------------
// B=4, N=4096, S=1024, NS=32, V=8, CIN=64, COUT=128, C1=70
#define NB 4
#define NP 4096
#define NSAMP 1024
#define KNS 32
#define NV 8

// ---------------- device scratch (static; no runtime allocs) ----------------
__device__ float  g_newxyz[NB * NSAMP * 3];
__device__ int    g_idx[NB * NSAMP * KNS];
__device__ float  g_pre2[(size_t)NB * NSAMP * KNS * 128];   // 67 MB
__device__ double g_acc1[128];    // [0:64) sum, [64:128) sumsq
__device__ double g_acc2[256];    // [0:128) sum, [128:256) sumsq
__device__ float  g_E[192];       // E[d][c] d=0..2, c=0..63
__device__ float  g_Kv[NV * 64];
__device__ float  g_scale1[64], g_shift1[64];
__device__ float  g_scale2[128], g_shift2[128];

// ---------------- k_prep: zero accumulators, fold m1 first-layer weights ----
__global__ void k_prep(const float* __restrict__ w1_0,
                       const float* __restrict__ b1_0,
                       const float* __restrict__ fp) {
    int t = threadIdx.x;             // 256 threads
    if (t < 128) g_acc1[t] = 0.0;
    g_acc2[t] = 0.0;
    if (t < 192) {
        int d = t >> 6, c = t & 63;
        // E = (w[3+d] - w[d]) + w[7+d]
        g_E[t] = (w1_0[(3 + d) * 64 + c] - w1_0[d * 64 + c]) + w1_0[(7 + d) * 64 + c];
    }
    if (t < 64) {
        for (int v = 0; v < NV; v++) {
            float s = b1_0[t];
            for (int d = 0; d < 3; d++) {
                float wd = w1_0[(3 + d) * 64 + t] - w1_0[d * 64 + t];
                s += fp[v * 3 + d] * (w1_0[(10 + d) * 64 + t] - wd);
            }
            g_Kv[v * 64 + t] = s;
        }
    }
}

// ---------------- k_fps: farthest point sampling, 1 block / batch ----------
__global__ __launch_bounds__(256) void k_fps(const float* __restrict__ xyz) {
    int b = blockIdx.x, tid = threadIdx.x;
    const float* X = xyz + (size_t)b * NP * 3;
    float px[16], py[16], pz[16], mind[16];
#pragma unroll
    for (int i = 0; i < 16; i++) {
        int p = tid + 256 * i;
        px[i] = X[p * 3 + 0];
        py[i] = X[p * 3 + 1];
        pz[i] = X[p * 3 + 2];
        mind[i] = 1e10f;
    }
    __shared__ float s_p[3];
    __shared__ unsigned long long s_part[8];
    if (tid == 0) {
        s_p[0] = px[0]; s_p[1] = py[0]; s_p[2] = pz[0];   // point index 0
        float* o = g_newxyz + (size_t)b * NSAMP * 3;
        o[0] = px[0]; o[1] = py[0]; o[2] = pz[0];
    }
    __syncthreads();
    for (int it = 1; it < NSAMP; it++) {
        float cx = s_p[0], cy = s_p[1], cz = s_p[2];
        unsigned long long best = 0ull;
#pragma unroll
        for (int i = 0; i < 16; i++) {
            float dx = px[i] - cx, dy = py[i] - cy, dz = pz[i] - cz;
            float d = fmaf(dz, dz, fmaf(dy, dy, dx * dx));
            float m = fminf(mind[i], d);
            mind[i] = m;
            unsigned long long kk =
                ((unsigned long long)__float_as_uint(m) << 32) |
                (unsigned)(0xFFFFFFFFu - (unsigned)(tid + 256 * i));
            best = best > kk ? best : kk;
        }
#pragma unroll
        for (int o = 16; o > 0; o >>= 1) {
            unsigned long long t = __shfl_xor_sync(FULL, best, o);
            best = best > t ? best : t;
        }
        if ((tid & 31) == 0) s_part[tid >> 5] = best;
        __syncthreads();
        if (tid == 0) {
            unsigned long long bb = s_part[0];
#pragma unroll
            for (int w = 1; w < 8; w++) {
                unsigned long long t = s_part[w];
                bb = bb > t ? bb : t;
            }
            int bi = (int)(0xFFFFFFFFu - (unsigned)(bb & 0xFFFFFFFFull));
            float x = X[bi * 3 + 0], y = X[bi * 3 + 1], z = X[bi * 3 + 2];
            s_p[0] = x; s_p[1] = y; s_p[2] = z;
            float* o = g_newxyz + ((size_t)b * NSAMP + it) * 3;
            o[0] = x; o[1] = y; o[2] = z;
        }
        __syncthreads();
    }
}

// ---------------- k_ball: first-32-in-index-order within radius, warp/query -
__global__ __launch_bounds__(256) void k_ball(const float* __restrict__ xyz) {
    int q = blockIdx.x * 8 + (threadIdx.x >> 5);   // 0..4095
    int lane = threadIdx.x & 31;
    int b = q >> 10;
    const float* X = xyz + (size_t)b * NP * 3;
    float qx = g_newxyz[q * 3 + 0], qy = g_newxyz[q * 3 + 1], qz = g_newxyz[q * 3 + 2];
    const float R2 = (float)(0.2 * 0.2);
    int found = 0;
    unsigned lmask = (1u << lane) - 1u;
    for (int base = 0; base < NP && found < KNS; base += 32) {
        int p = base + lane;
        float dx = X[p * 3 + 0] - qx, dy = X[p * 3 + 1] - qy, dz = X[p * 3 + 2] - qz;
        float d = fmaf(dz, dz, fmaf(dy, dy, dx * dx));
        bool in = d < R2;
        unsigned m = __ballot_sync(FULL, in);
        if (in) {
            int pos = found + __popc(m & lmask);
            if (pos < KNS) g_idx[q * KNS + pos] = p;
        }
        found += __popc(m);
    }
    if (found > KNS) found = KNS;
    for (int k2 = found + lane; k2 < KNS; k2 += 32) g_idx[q * KNS + k2] = -1;
}

// ---------------- k_stats1: BN1 global sums over 1M rows x 64ch ------------
__global__ __launch_bounds__(256) void k_stats1(const float* __restrict__ xyz,
                                                const float* __restrict__ fp,
                                                const float* __restrict__ w1_0) {
    __shared__ double ssm[64], ssq[64];
    int tid = threadIdx.x;
    int c = tid & 63, slot = tid >> 6;
    if (tid < 64) { ssm[tid] = 0.0; ssq[tid] = 0.0; }
    float Ex = g_E[c], Ey = g_E[64 + c], Ez = g_E[128 + c];
    float w6 = w1_0[6 * 64 + c];
    float Kv[NV];
#pragma unroll
    for (int v = 0; v < NV; v++) Kv[v] = g_Kv[v * 64 + c];
    float fx[NV], fy[NV], fz[NV];
#pragma unroll
    for (int v = 0; v < NV; v++) { fx[v] = fp[v * 3]; fy[v] = fp[v * 3 + 1]; fz[v] = fp[v * 3 + 2]; }
    float sm = 0.f, sq = 0.f;
    int row0 = blockIdx.x * 64 + slot * 16;
    for (int it = 0; it < 16; it++) {
        int row = row0 + it;
        int idx = g_idx[row];
        float gx = 0.f, gy = 0.f, gz = 0.f;
        if (idx >= 0) {
            int b = row >> 15;
            const float* P = xyz + ((size_t)(b << 12) + idx) * 3;
            gx = P[0]; gy = P[1]; gz = P[2];
        }
        float base = fmaf(gz, Ez, fmaf(gy, Ey, gx * Ex));
#pragma unroll
        for (int v = 0; v < NV; v++) {
            float ax = gx - fx[v], ay = gy - fy[v], az = gz - fz[v];
            float e = sqrtf(fmaf(az, az, fmaf(ay, ay, ax * ax)));
            float pre = base + fmaf(e, w6, Kv[v]);
            sm += pre;
            sq = fmaf(pre, pre, sq);
        }
    }
    __syncthreads();
    atomicAdd(&ssm[c], (double)sm);
    atomicAdd(&ssq[c], (double)sq);
    __syncthreads();
    if (tid < 64) {
        atomicAdd(&g_acc1[tid], ssm[tid]);
        atomicAdd(&g_acc1[64 + tid], ssq[tid]);
    }
}

__global__ void k_fin1(const float* __restrict__ g1, const float* __restrict__ bt1) {
    int c = threadIdx.x;   // 64
    double n = 1048576.0;
    double mean = g_acc1[c] / n;
    double var = g_acc1[64 + c] / n - mean * mean;
    float sc = (float)((double)g1[c] / sqrt(var + 1e-5));
    g_scale1[c] = sc;
    g_shift1[c] = (float)((double)bt1[c] - mean * (double)sc);
}

// ---------------- k_main: per-row m1 MLP + attention + m2 first layer -------
__global__ __launch_bounds__(256) void k_main(const float* __restrict__ xyz,
                                              const float* __restrict__ f,
                                              const float* __restrict__ fp,
                                              const float* __restrict__ w1_0,
                                              const float* __restrict__ w1_1,
                                              const float* __restrict__ b1_1,
                                              const float* __restrict__ w2_0,
                                              const float* __restrict__ b2_0) {
    __shared__ double ssm2[128], ssq2[128];
    int tid = threadIdx.x;
    if (tid < 128) { ssm2[tid] = 0.0; ssq2[tid] = 0.0; }
    __syncthreads();

    int row = blockIdx.x * 8 + (tid >> 5);
    int lane = tid & 31;
    int q = row >> 5;
    int b = row >> 15;
    int idx = g_idx[row];

    float gx = 0.f, gy = 0.f, gz = 0.f;
    if (idx >= 0) {
        const float* P = xyz + ((size_t)(b << 12) + idx) * 3;
        gx = P[0]; gy = P[1]; gz = P[2];
    }
    float nx = g_newxyz[q * 3 + 0], ny = g_newxyz[q * 3 + 1], nz = g_newxyz[q * 3 + 2];
    float lx = gx - nx, ly = gy - ny, lz = gz - nz;

    const float* FF = f + ((size_t)(b << 12) + (idx < 0 ? 0 : idx)) * 64;
    // gf channel ownership: lane -> j=lane, j=lane+32, (lane<6) j=lane+64
    float gf0;
    if (lane >= 6)      gf0 = (idx >= 0) ? FF[lane - 6] : 0.f;
    else if (lane == 0) gf0 = gx;
    else if (lane == 1) gf0 = gy;
    else if (lane == 2) gf0 = gz;
    else if (lane == 3) gf0 = lx;
    else if (lane == 4) gf0 = ly;
    else                gf0 = lz;
    float gf1 = (idx >= 0) ? FF[lane + 26] : 0.f;
    float gf2 = (lane < 6 && idx >= 0) ? FF[lane + 58] : 0.f;

    // h1 for channels c0=lane, c1=lane+32, all 8 frame vectors
    int c0 = lane, c1 = lane + 32;
    float E00 = g_E[c0], E10 = g_E[64 + c0], E20 = g_E[128 + c0];
    float E01 = g_E[c1], E11 = g_E[64 + c1], E21 = g_E[128 + c1];
    float w60 = w1_0[6 * 64 + c0], w61 = w1_0[6 * 64 + c1];
    float sc0 = g_scale1[c0], sh0 = g_shift1[c0];
    float sc1 = g_scale1[c1], sh1 = g_shift1[c1];
    float base0 = fmaf(gz, E20, fmaf(gy, E10, gx * E00));
    float base1 = fmaf(gz, E21, fmaf(gy, E11, gx * E01));
    float h0[NV], h1r[NV];
#pragma unroll
    for (int v = 0; v < NV; v++) {
        float fx = fp[v * 3], fy = fp[v * 3 + 1], fz = fp[v * 3 + 2];
        float ax = gx - fx, ay = gy - fy, az = gz - fz;
        float e = sqrtf(fmaf(az, az, fmaf(ay, ay, ax * ax)));
        float p0 = base0 + fmaf(e, w60, g_Kv[v * 64 + c0]);
        float p1 = base1 + fmaf(e, w61, g_Kv[v * 64 + c1]);
        h0[v] = fmaxf(0.f, fmaf(p0, sc0, sh0));
        h1r[v] = fmaxf(0.f, fmaf(p1, sc1, sh1));
    }

    // a = h1 @ w1_1 + b1_1  (70 outputs; lane owns 3)
    float A0[NV], A1[NV], A2[NV];
    float bb0 = b1_1[lane], bb1 = b1_1[lane + 32];
    float bb2 = (lane < 6) ? b1_1[64 + lane] : 0.f;
#pragma unroll
    for (int v = 0; v < NV; v++) { A0[v] = bb0; A1[v] = bb1; A2[v] = bb2; }
#pragma unroll 4
    for (int c = 0; c < 32; c++) {
        float wA = w1_1[c * 70 + lane];
        float wB = w1_1[c * 70 + 32 + lane];
        float wC = (lane < 6) ? w1_1[c * 70 + 64 + lane] : 0.f;
#pragma unroll
        for (int v = 0; v < NV; v++) {
            float hv = __shfl_sync(FULL, h0[v], c);
            A0[v] = fmaf(hv, wA, A0[v]);
            A1[v] = fmaf(hv, wB, A1[v]);
            A2[v] = fmaf(hv, wC, A2[v]);
        }
    }
#pragma unroll 4
    for (int c = 0; c < 32; c++) {
        float wA = w1_1[(c + 32) * 70 + lane];
        float wB = w1_1[(c + 32) * 70 + 32 + lane];
        float wC = (lane < 6) ? w1_1[(c + 32) * 70 + 64 + lane] : 0.f;
#pragma unroll
        for (int v = 0; v < NV; v++) {
            float hv = __shfl_sync(FULL, h1r[v], c);
            A0[v] = fmaf(hv, wA, A0[v]);
            A1[v] = fmaf(hv, wB, A1[v]);
            A2[v] = fmaf(hv, wC, A2[v]);
        }
    }

    // p = gf * a ; softmax over V per channel; agg = sum(softmax*p)
#pragma unroll
    for (int v = 0; v < NV; v++) { A0[v] *= gf0; A1[v] *= gf1; A2[v] *= gf2; }
    float agg0, agg1, agg2;
    {
        float mx = A0[0];
#pragma unroll
        for (int v = 1; v < NV; v++) mx = fmaxf(mx, A0[v]);
        float se = 0.f, sp = 0.f;
        float ev[NV];
#pragma unroll
        for (int v = 0; v < NV; v++) { ev[v] = expf(A0[v] - mx); se += ev[v]; }
#pragma unroll
        for (int v = 0; v < NV; v++) sp = fmaf(ev[v] / se, A0[v], sp);
        agg0 = sp;
    }
    {
        float mx = A1[0];
#pragma unroll
        for (int v = 1; v < NV; v++) mx = fmaxf(mx, A1[v]);
        float se = 0.f, sp = 0.f;
        float ev[NV];
#pragma unroll
        for (int v = 0; v < NV; v++) { ev[v] = expf(A1[v] - mx); se += ev[v]; }
#pragma unroll
        for (int v = 0; v < NV; v++) sp = fmaf(ev[v] / se, A1[v], sp);
        agg1 = sp;
    }
    {
        float mx = A2[0];
#pragma unroll
        for (int v = 1; v < NV; v++) mx = fmaxf(mx, A2[v]);
        float se = 0.f, sp = 0.f;
        float ev[NV];
#pragma unroll
        for (int v = 0; v < NV; v++) { ev[v] = expf(A2[v] - mx); se += ev[v]; }
#pragma unroll
        for (int v = 0; v < NV; v++) sp = fmaf(ev[v] / se, A2[v], sp);
        agg2 = sp;
    }
    if (idx < 0) { agg0 = 0.f; agg1 = 0.f; agg2 = 0.f; }   // where(mask, 0, agg)

    // pre2 = agg @ w2_0 + b2_0  (128 outputs; lane owns 4)
    float acc0 = b2_0[lane], acc1 = b2_0[lane + 32];
    float acc2 = b2_0[lane + 64], acc3 = b2_0[lane + 96];
#pragma unroll 4
    for (int j = 0; j < 32; j++) {
        float aj = __shfl_sync(FULL, agg0, j);
        const float* W = w2_0 + j * 128;
        acc0 = fmaf(aj, W[lane], acc0);
        acc1 = fmaf(aj, W[lane + 32], acc1);
        acc2 = fmaf(aj, W[lane + 64], acc2);
        acc3 = fmaf(aj, W[lane + 96], acc3);
    }
#pragma unroll 4
    for (int j = 0; j < 32; j++) {
        float aj = __shfl_sync(FULL, agg1, j);
        const float* W = w2_0 + (j + 32) * 128;
        acc0 = fmaf(aj, W[lane], acc0);
        acc1 = fmaf(aj, W[lane + 32], acc1);
        acc2 = fmaf(aj, W[lane + 64], acc2);
        acc3 = fmaf(aj, W[lane + 96], acc3);
    }
#pragma unroll
    for (int j = 0; j < 6; j++) {
        float aj = __shfl_sync(FULL, agg2, j);
        const float* W = w2_0 + (j + 64) * 128;
        acc0 = fmaf(aj, W[lane], acc0);
        acc1 = fmaf(aj, W[lane + 32], acc1);
        acc2 = fmaf(aj, W[lane + 64], acc2);
        acc3 = fmaf(aj, W[lane + 96], acc3);
    }

    float* P2 = g_pre2 + (size_t)row * 128;
    P2[lane] = acc0; P2[lane + 32] = acc1; P2[lane + 64] = acc2; P2[lane + 96] = acc3;

    // BN2 stats
    atomicAdd(&ssm2[lane], (double)acc0);       atomicAdd(&ssq2[lane], (double)acc0 * acc0);
    atomicAdd(&ssm2[lane + 32], (double)acc1);  atomicAdd(&ssq2[lane + 32], (double)acc1 * acc1);
    atomicAdd(&ssm2[lane + 64], (double)acc2);  atomicAdd(&ssq2[lane + 64], (double)acc2 * acc2);
    atomicAdd(&ssm2[lane + 96], (double)acc3);  atomicAdd(&ssq2[lane + 96], (double)acc3 * acc3);
    __syncthreads();
    if (tid < 128) {
        atomicAdd(&g_acc2[tid], ssm2[tid]);
        atomicAdd(&g_acc2[128 + tid], ssq2[tid]);
    }
}

__global__ void k_fin2(const float* __restrict__ g2, const float* __restrict__ bt2) {
    int c = threadIdx.x;   // 128
    double n = 131072.0;
    double mean = g_acc2[c] / n;
    double var = g_acc2[128 + c] / n - mean * mean;
    float sc = (float)((double)g2[c] / sqrt(var + 1e-5));
    g_scale2[c] = sc;
    g_shift2[c] = (float)((double)bt2[c] - mean * (double)sc);
}

// ---------------- k_final: m2 second layer + residual + gelu + max over NS --
__global__ __launch_bounds__(128) void k_final(const float* __restrict__ f,
                                               const float* __restrict__ w2_1,
                                               const float* __restrict__ b2_1,
                                               const float* __restrict__ res_w,
                                               const float* __restrict__ res_b,
                                               float* __restrict__ out,
                                               int out_size) {
    __shared__ float s_wm[KNS][128];
    __shared__ float s_gf[KNS][64];
    __shared__ float s_red[4][128];
    int q = blockIdx.x;           // 0..4095
    int tid = threadIdx.x;        // 128
    int b = q >> 10;
    int kg = tid & 31;            // k-group -> k4 = kg*4
    int rg = tid >> 5;            // row group: rows rg*8 .. rg*8+7
    int k4 = kg * 4;

    // stage wmid = relu(bn2(pre2)) for 32 rows
    for (int t = tid; t < KNS * 128; t += 128) {
        int r = t >> 7, k = t & 127;
        float pre = g_pre2[((size_t)q * KNS + r) * 128 + k];
        s_wm[r][k] = fmaxf(0.f, fmaf(pre, g_scale2[k], g_shift2[k]));
    }
    // stage grouped_feature for 32 rows
    for (int t = tid; t < KNS * 64; t += 128) {
        int r = t >> 6, k = t & 63;
        int id = g_idx[q * KNS + r];
        s_gf[r][k] = (id < 0) ? 0.f : f[((size_t)(b << 12) + id) * 64 + k];
    }
    __syncthreads();

    float acc[8][4];
#pragma unroll
    for (int r = 0; r < 8; r++)
#pragma unroll
        for (int m = 0; m < 4; m++)
            acc[r][m] = b2_1[k4 + m] + res_b[k4 + m];

    for (int j = 0; j < 128; j++) {
        float4 w = *(const float4*)&w2_1[j * 128 + k4];
#pragma unroll
        for (int r = 0; r < 8; r++) {
            float wm = s_wm[rg * 8 + r][j];
            acc[r][0] = fmaf(wm, w.x, acc[r][0]);
            acc[r][1] = fmaf(wm, w.y, acc[r][1]);
            acc[r][2] = fmaf(wm, w.z, acc[r][2]);
            acc[r][3] = fmaf(wm, w.w, acc[r][3]);
        }
    }
    for (int j = 0; j < 64; j++) {
        float4 w = *(const float4*)&res_w[j * 128 + k4];
#pragma unroll
        for (int r = 0; r < 8; r++) {
            float gv = s_gf[rg * 8 + r][j];
            acc[r][0] = fmaf(gv, w.x, acc[r][0]);
            acc[r][1] = fmaf(gv, w.y, acc[r][1]);
            acc[r][2] = fmaf(gv, w.z, acc[r][2]);
            acc[r][3] = fmaf(gv, w.w, acc[r][3]);
        }
    }

    // exact-erf gelu + partial max over this row group
#pragma unroll
    for (int m = 0; m < 4; m++) {
        float mxv = -INFINITY;
#pragma unroll
        for (int r = 0; r < 8; r++) {
            float x = acc[r][m];
            float gl = 0.5f * x * (1.f + erff(x * 0.70710678118654752440f));
            mxv = fmaxf(mxv, gl);
        }
        s_red[rg][k4 + m] = mxv;
    }
    __syncthreads();
    {
        float m0 = fmaxf(fmaxf(s_red[0][tid], s_red[1][tid]),
                         fmaxf(s_red[2][tid], s_red[3][tid]));
        out[(size_t)q * 128 + tid] = m0;
    }
    // second output: new_xyz, appended after new_f (guarded by out_size)
    if (tid < 3 && out_size >= NB * NSAMP * 128 + NB * NSAMP * 3) {
        out[(size_t)NB * NSAMP * 128 + q * 3 + tid] = g_newxyz[q * 3 + tid];
    }
}

// ---------------- host launcher ----------------
extern "C" void kernel_launch(void* const* d_in, const int* in_sizes, int n_in,
                              void* d_out, int out_size) {
    const float* xyz   = (const float*)d_in[0];
    const float* f     = (const float*)d_in[1];
    const float* fp    = (const float*)d_in[2];
    const float* w1_0  = (const float*)d_in[3];
    const float* b1_0  = (const float*)d_in[4];
    const float* g1_0  = (const float*)d_in[5];
    const float* bt1_0 = (const float*)d_in[6];
    const float* w1_1  = (const float*)d_in[7];
    const float* b1_1  = (const float*)d_in[8];
    const float* w2_0  = (const float*)d_in[9];
    const float* b2_0  = (const float*)d_in[10];
    const float* g2_0  = (const float*)d_in[11];
    const float* bt2_0 = (const float*)d_in[12];
    const float* w2_1  = (const float*)d_in[13];
    const float* b2_1  = (const float*)d_in[14];
    const float* res_w = (const float*)d_in[15];
    const float* res_b = (const float*)d_in[16];
    float* out = (float*)d_out;
    (void)in_sizes; (void)n_in;

    k_prep<<<1, 256>>>(w1_0, b1_0, fp);
    k_fps<<<NB, 256>>>(xyz);
    k_ball<<<(NB * NSAMP) / 8, 256>>>(xyz);
    k_stats1<<<(NB * NSAMP * KNS) / 64, 256>>>(xyz, fp, w1_0);
    k_fin1<<<1, 64>>>(g1_0, bt1_0);
    k_main<<<(NB * NSAMP * KNS) / 8, 256>>>(xyz, f, fp, w1_0, w1_1, b1_1, w2_0, b2_0);
    k_fin2<<<1, 128>>>(g2_0, bt2_0);
    k_final<<<NB * NSAMP, 128>>>(f, w2_1, b2_1, res_w, res_b, out, out_size);
}

// round 11
// speedup vs baseline: 1.3730x; 1.3730x over previous
#include <cuda_runtime.h>
#include <math.h>

#define FULL 0xffffffffu

// B=4, N=4096, S=1024, NS=32, V=8, CIN=64, COUT=128, C1=70
#define NB 4
#define NP 4096
#define NSAMP 1024
#define KNS 32
#define NV 8
#define NPTS (NB * NP)            // 16384
#define NROWS (NB * NSAMP * KNS)  // 131072

// ---------------- device scratch (static) ----------------
__device__ float  g_newxyz[NB * NSAMP * 3];
__device__ int    g_idx[NROWS];
__device__ float  g_pre2[(size_t)NROWS * 128];     // 67 MB
__device__ float  g_A[(size_t)NPTS * 70 * 8];      // 36.7 MB  [point][j][v]
__device__ float  g_res[(size_t)NPTS * 128];       // 8.4 MB
__device__ int    g_cnt[NPTS];
__device__ int    g_mcnt;
__device__ double g_acc1[128];    // [0:64) sum, [64:128) sumsq
__device__ double g_acc2[256];    // [0:128) sum, [128:256) sumsq
__device__ float  g_E[192];
__device__ float  g_Kv[NV * 64];
__device__ float  g_scale1[64], g_shift1[64];
__device__ float  g_scale2[128], g_shift2[128];

// ---------------- k_prep ----------------
__global__ void k_prep(const float* __restrict__ w1_0,
                       const float* __restrict__ b1_0,
                       const float* __restrict__ fp) {
    int t = threadIdx.x;             // 256
    if (t < 128) g_acc1[t] = 0.0;
    g_acc2[t] = 0.0;
    for (int i = t; i < NPTS; i += 256) g_cnt[i] = 0;
    if (t == 0) g_mcnt = 0;
    if (t < 192) {
        int d = t >> 6, c = t & 63;
        g_E[t] = (w1_0[(3 + d) * 64 + c] - w1_0[d * 64 + c]) + w1_0[(7 + d) * 64 + c];
    }
    if (t < 64) {
        for (int v = 0; v < NV; v++) {
            float s = b1_0[t];
            for (int d = 0; d < 3; d++) {
                float wd = w1_0[(3 + d) * 64 + t] - w1_0[d * 64 + t];
                s += fp[v * 3 + d] * (w1_0[(10 + d) * 64 + t] - wd);
            }
            g_Kv[v * 64 + t] = s;
        }
    }
}

// ---------------- k_fps: one barrier per iteration ----------------
__global__ __launch_bounds__(256) void k_fps(const float* __restrict__ xyz) {
    int b = blockIdx.x, tid = threadIdx.x;
    const float* X = xyz + (size_t)b * NP * 3;
    float px[16], py[16], pz[16], mind[16];
    unsigned inv[16];
#pragma unroll
    for (int i = 0; i < 16; i++) {
        int p = tid + 256 * i;
        px[i] = X[p * 3 + 0];
        py[i] = X[p * 3 + 1];
        pz[i] = X[p * 3 + 2];
        mind[i] = 1e10f;
        inv[i] = 0xFFFFFFFFu - (unsigned)p;
    }
    __shared__ unsigned long long s_part[2][8];
    float cx = X[0], cy = X[1], cz = X[2];     // point index 0
    if (tid == 0) {
        float* o = g_newxyz + (size_t)b * NSAMP * 3;
        o[0] = cx; o[1] = cy; o[2] = cz;
    }
    int wid = tid >> 5, lane = tid & 31;
    for (int it = 1; it < NSAMP; it++) {
        unsigned long long best = 0ull;
#pragma unroll
        for (int i = 0; i < 16; i++) {
            float dx = px[i] - cx, dy = py[i] - cy, dz = pz[i] - cz;
            float d = fmaf(dz, dz, fmaf(dy, dy, dx * dx));
            float m = fminf(mind[i], d);
            mind[i] = m;
            unsigned long long kk =
                ((unsigned long long)__float_as_uint(m) << 32) | inv[i];
            best = best > kk ? best : kk;
        }
#pragma unroll
        for (int o = 16; o > 0; o >>= 1) {
            unsigned long long t = __shfl_xor_sync(FULL, best, o);
            best = best > t ? best : t;
        }
        if (lane == 0) s_part[it & 1][wid] = best;
        __syncthreads();
        unsigned long long bb = s_part[it & 1][0];
#pragma unroll
        for (int w = 1; w < 8; w++) {
            unsigned long long t = s_part[it & 1][w];
            bb = bb > t ? bb : t;
        }
        int bi = (int)(0xFFFFFFFFu - (unsigned)(bb & 0xFFFFFFFFull));
        cx = X[bi * 3 + 0]; cy = X[bi * 3 + 1]; cz = X[bi * 3 + 2];
        if (tid == 0) {
            float* o = g_newxyz + ((size_t)b * NSAMP + it) * 3;
            o[0] = cx; o[1] = cy; o[2] = cz;
        }
    }
}

// ---------------- k_ball ----------------
__global__ __launch_bounds__(256) void k_ball(const float* __restrict__ xyz) {
    int q = blockIdx.x * 8 + (threadIdx.x >> 5);
    int lane = threadIdx.x & 31;
    int b = q >> 10;
    const float* X = xyz + (size_t)b * NP * 3;
    float qx = g_newxyz[q * 3 + 0], qy = g_newxyz[q * 3 + 1], qz = g_newxyz[q * 3 + 2];
    const float R2 = (float)(0.2 * 0.2);
    int found = 0;
    unsigned lmask = (1u << lane) - 1u;
    for (int base = 0; base < NP && found < KNS; base += 32) {
        int p = base + lane;
        float dx = X[p * 3 + 0] - qx, dy = X[p * 3 + 1] - qy, dz = X[p * 3 + 2] - qz;
        float d = fmaf(dz, dz, fmaf(dy, dy, dx * dx));
        bool in = d < R2;
        unsigned m = __ballot_sync(FULL, in);
        if (in) {
            int pos = found + __popc(m & lmask);
            if (pos < KNS) g_idx[q * KNS + pos] = p;
        }
        found += __popc(m);
    }
    if (found > KNS) found = KNS;
    for (int k2 = found + lane; k2 < KNS; k2 += 32) g_idx[q * KNS + k2] = -1;
}

// ---------------- k_hist: per-point multiplicity + masked count ----------
__global__ __launch_bounds__(256) void k_hist() {
    int t = blockIdx.x * 256 + threadIdx.x;   // 0..131071
    int idx = g_idx[t];
    bool masked = idx < 0;
    unsigned mm = __ballot_sync(FULL, masked);
    if (!masked) atomicAdd(&g_cnt[((t >> 15) << 12) + idx], 1);
    if ((threadIdx.x & 31) == 0 && mm) atomicAdd(&g_mcnt, __popc(mm));
}

// ---------------- k_stats1w: BN1 sums, count-weighted over 16K points ----
__global__ __launch_bounds__(256) void k_stats1w(const float* __restrict__ xyz,
                                                 const float* __restrict__ fp,
                                                 const float* __restrict__ w1_0) {
    __shared__ double ssm[64], ssq[64];
    int tid = threadIdx.x;
    int c = tid & 63, slot = tid >> 6;
    if (tid < 64) { ssm[tid] = 0.0; ssq[tid] = 0.0; }
    __syncthreads();
    float Ex = g_E[c], Ey = g_E[64 + c], Ez = g_E[128 + c];
    float w6 = w1_0[6 * 64 + c];
    float Kv[NV];
#pragma unroll
    for (int v = 0; v < NV; v++) Kv[v] = g_Kv[v * 64 + c];
    float fx[NV], fy[NV], fz[NV];
#pragma unroll
    for (int v = 0; v < NV; v++) { fx[v] = fp[v * 3]; fy[v] = fp[v * 3 + 1]; fz[v] = fp[v * 3 + 2]; }
    double sm = 0.0, sq = 0.0;
    int p0 = blockIdx.x * 256 + slot * 64;    // 64 blocks
    for (int i = 0; i < 64; i++) {
        int p = p0 + i;
        int w = g_cnt[p];
        if (!w) continue;
        float gx = xyz[p * 3], gy = xyz[p * 3 + 1], gz = xyz[p * 3 + 2];
        float base = fmaf(gz, Ez, fmaf(gy, Ey, gx * Ex));
        float lsm = 0.f, lsq = 0.f;
#pragma unroll
        for (int v = 0; v < NV; v++) {
            float ax = gx - fx[v], ay = gy - fy[v], az = gz - fz[v];
            float e = sqrtf(fmaf(az, az, fmaf(ay, ay, ax * ax)));
            float pre = base + fmaf(e, w6, Kv[v]);
            lsm += pre;
            lsq = fmaf(pre, pre, lsq);
        }
        sm += (double)w * lsm;
        sq += (double)w * lsq;
    }
    atomicAdd(&ssm[c], sm);
    atomicAdd(&ssq[c], sq);
    __syncthreads();
    if (tid < 64) {
        atomicAdd(&g_acc1[tid], ssm[tid]);
        atomicAdd(&g_acc1[64 + tid], ssq[tid]);
    }
}

__global__ void k_fin1(const float* __restrict__ g1, const float* __restrict__ bt1,
                       const float* __restrict__ fp, const float* __restrict__ w1_0) {
    int c = threadIdx.x;   // 64
    double M = (double)g_mcnt;       // masked rows (each has 8 v samples)
    double s = g_acc1[c], ss = g_acc1[64 + c];
    float w6 = w1_0[6 * 64 + c];
#pragma unroll
    for (int v = 0; v < NV; v++) {
        float ax = 0.f - fp[v * 3], ay = 0.f - fp[v * 3 + 1], az = 0.f - fp[v * 3 + 2];
        float e = sqrtf(fmaf(az, az, fmaf(ay, ay, ax * ax)));
        float pre = fmaf(e, w6, g_Kv[v * 64 + c]);   // base = 0
        s += M * (double)pre;
        ss += M * (double)pre * pre;
    }
    double n = 1048576.0;
    double mean = s / n;
    double var = ss / n - mean * mean;
    float sc = (float)((double)g1[c] / sqrt(var + 1e-5));
    g_scale1[c] = sc;
    g_shift1[c] = (float)((double)bt1[c] - mean * (double)sc);
}

// ---------------- k_pointA: per-point m1 MLP -> A[point][70][8] ----------
__global__ __launch_bounds__(256) void k_pointA(const float* __restrict__ xyz,
                                                const float* __restrict__ fp,
                                                const float* __restrict__ w1_0,
                                                const float* __restrict__ w1_1,
                                                const float* __restrict__ b1_1) {
    int p = blockIdx.x * 8 + (threadIdx.x >> 5);   // 0..16383
    int lane = threadIdx.x & 31;
    const float* P = xyz + (size_t)p * 3;
    float gx = P[0], gy = P[1], gz = P[2];

    int c0 = lane, c1 = lane + 32;
    float E00 = g_E[c0], E10 = g_E[64 + c0], E20 = g_E[128 + c0];
    float E01 = g_E[c1], E11 = g_E[64 + c1], E21 = g_E[128 + c1];
    float w60 = w1_0[6 * 64 + c0], w61 = w1_0[6 * 64 + c1];
    float sc0 = g_scale1[c0], sh0 = g_shift1[c0];
    float sc1 = g_scale1[c1], sh1 = g_shift1[c1];
    float base0 = fmaf(gz, E20, fmaf(gy, E10, gx * E00));
    float base1 = fmaf(gz, E21, fmaf(gy, E11, gx * E01));
    float h0[NV], h1r[NV];
#pragma unroll
    for (int v = 0; v < NV; v++) {
        float fx = fp[v * 3], fy = fp[v * 3 + 1], fz = fp[v * 3 + 2];
        float ax = gx - fx, ay = gy - fy, az = gz - fz;
        float e = sqrtf(fmaf(az, az, fmaf(ay, ay, ax * ax)));
        float p0 = base0 + fmaf(e, w60, g_Kv[v * 64 + c0]);
        float p1 = base1 + fmaf(e, w61, g_Kv[v * 64 + c1]);
        h0[v] = fmaxf(0.f, fmaf(p0, sc0, sh0));
        h1r[v] = fmaxf(0.f, fmaf(p1, sc1, sh1));
    }

    float A0[NV], A1[NV], A2[NV];
    float bb0 = b1_1[lane], bb1 = b1_1[lane + 32];
    float bb2 = (lane < 6) ? b1_1[64 + lane] : 0.f;
#pragma unroll
    for (int v = 0; v < NV; v++) { A0[v] = bb0; A1[v] = bb1; A2[v] = bb2; }
#pragma unroll 4
    for (int c = 0; c < 32; c++) {
        float wA = w1_1[c * 70 + lane];
        float wB = w1_1[c * 70 + 32 + lane];
        float wC = (lane < 6) ? w1_1[c * 70 + 64 + lane] : 0.f;
#pragma unroll
        for (int v = 0; v < NV; v++) {
            float hv = __shfl_sync(FULL, h0[v], c);
            A0[v] = fmaf(hv, wA, A0[v]);
            A1[v] = fmaf(hv, wB, A1[v]);
            A2[v] = fmaf(hv, wC, A2[v]);
        }
    }
#pragma unroll 4
    for (int c = 0; c < 32; c++) {
        float wA = w1_1[(c + 32) * 70 + lane];
        float wB = w1_1[(c + 32) * 70 + 32 + lane];
        float wC = (lane < 6) ? w1_1[(c + 32) * 70 + 64 + lane] : 0.f;
#pragma unroll
        for (int v = 0; v < NV; v++) {
            float hv = __shfl_sync(FULL, h1r[v], c);
            A0[v] = fmaf(hv, wA, A0[v]);
            A1[v] = fmaf(hv, wB, A1[v]);
            A2[v] = fmaf(hv, wC, A2[v]);
        }
    }

    float* d0 = g_A + ((size_t)p * 70 + lane) * 8;
    *(float4*)d0       = make_float4(A0[0], A0[1], A0[2], A0[3]);
    *(float4*)(d0 + 4) = make_float4(A0[4], A0[5], A0[6], A0[7]);
    float* d1 = g_A + ((size_t)p * 70 + 32 + lane) * 8;
    *(float4*)d1       = make_float4(A1[0], A1[1], A1[2], A1[3]);
    *(float4*)(d1 + 4) = make_float4(A1[4], A1[5], A1[6], A1[7]);
    if (lane < 6) {
        float* d2 = g_A + ((size_t)p * 70 + 64 + lane) * 8;
        *(float4*)d2       = make_float4(A2[0], A2[1], A2[2], A2[3]);
        *(float4*)(d2 + 4) = make_float4(A2[4], A2[5], A2[6], A2[7]);
    }
}

// ---------------- k_pointres: res[point] = f[point] @ res_w -------------
__global__ __launch_bounds__(256) void k_pointres(const float* __restrict__ f,
                                                  const float* __restrict__ res_w) {
    int p = blockIdx.x * 8 + (threadIdx.x >> 5);
    int lane = threadIdx.x & 31;
    int k4 = lane * 4;
    const float* FF = f + (size_t)p * 64;
    float f0 = FF[lane], f1 = FF[lane + 32];
    float4 acc = make_float4(0.f, 0.f, 0.f, 0.f);
#pragma unroll 8
    for (int j = 0; j < 32; j++) {
        float fj = __shfl_sync(FULL, f0, j);
        float4 w = *(const float4*)&res_w[j * 128 + k4];
        acc.x = fmaf(fj, w.x, acc.x); acc.y = fmaf(fj, w.y, acc.y);
        acc.z = fmaf(fj, w.z, acc.z); acc.w = fmaf(fj, w.w, acc.w);
    }
#pragma unroll 8
    for (int j = 0; j < 32; j++) {
        float fj = __shfl_sync(FULL, f1, j);
        float4 w = *(const float4*)&res_w[(j + 32) * 128 + k4];
        acc.x = fmaf(fj, w.x, acc.x); acc.y = fmaf(fj, w.y, acc.y);
        acc.z = fmaf(fj, w.z, acc.z); acc.w = fmaf(fj, w.w, acc.w);
    }
    *(float4*)&g_res[(size_t)p * 128 + k4] = acc;
}

// ---------------- softmax helper ----------------
__device__ __forceinline__ float softagg8(const float x[8]) {
    float mx = x[0];
#pragma unroll
    for (int v = 1; v < NV; v++) mx = fmaxf(mx, x[v]);
    float e[NV], se = 0.f;
#pragma unroll
    for (int v = 0; v < NV; v++) { e[v] = __expf(x[v] - mx); se += e[v]; }
    float inv = 1.0f / se, sp = 0.f;
#pragma unroll
    for (int v = 0; v < NV; v++) sp = fmaf(e[v] * inv, x[v], sp);
    return sp;
}

// ---------------- k_main2: row softmax + agg@w2_0, BN2 stats -------------
__global__ __launch_bounds__(256) void k_main2(const float* __restrict__ xyz,
                                               const float* __restrict__ f,
                                               const float* __restrict__ w2_0,
                                               const float* __restrict__ b2_0) {
    __shared__ float s_w2[70 * 128];
    __shared__ double ssm[128], ssq[128];
    int tid = threadIdx.x, lane = tid & 31, wid = tid >> 5, k4 = lane * 4;
    for (int i = tid; i < 70 * 128; i += 256) s_w2[i] = w2_0[i];
    if (tid < 128) { ssm[tid] = 0.0; ssq[tid] = 0.0; }
    __syncthreads();
    float4 b4 = *(const float4*)&b2_0[k4];
    double sm0 = 0, sm1 = 0, sm2 = 0, sm3 = 0, sq0 = 0, sq1 = 0, sq2 = 0, sq3 = 0;
    int rbase = (blockIdx.x * 8 + wid) * 16;
    for (int r = 0; r < 16; r++) {
        int row = rbase + r;
        int idx = g_idx[row];
        float4 acc = b4;
        if (idx >= 0) {
            int p = ((row >> 15) << 12) + idx;
            const float* P = xyz + (size_t)p * 3;
            float gx = P[0], gy = P[1], gz = P[2];
            int q = row >> 5;
            float nx = g_newxyz[q * 3], ny = g_newxyz[q * 3 + 1], nz = g_newxyz[q * 3 + 2];
            const float* FF = f + (size_t)p * 64;
            float gf0;
            if (lane >= 6)      gf0 = FF[lane - 6];
            else if (lane == 0) gf0 = gx;
            else if (lane == 1) gf0 = gy;
            else if (lane == 2) gf0 = gz;
            else if (lane == 3) gf0 = gx - nx;
            else if (lane == 4) gf0 = gy - ny;
            else                gf0 = gz - nz;
            float gf1 = FF[lane + 26];
            float gf2 = (lane < 6) ? FF[lane + 58] : 0.f;

            const float* A0p = g_A + ((size_t)p * 70 + lane) * 8;
            const float* A1p = g_A + ((size_t)p * 70 + 32 + lane) * 8;
            float4 x0 = *(const float4*)A0p, x1 = *(const float4*)(A0p + 4);
            float4 y0 = *(const float4*)A1p, y1 = *(const float4*)(A1p + 4);
            float4 z0 = make_float4(0.f, 0.f, 0.f, 0.f), z1 = z0;
            if (lane < 6) {
                const float* A2p = g_A + ((size_t)p * 70 + 64 + lane) * 8;
                z0 = *(const float4*)A2p; z1 = *(const float4*)(A2p + 4);
            }
            float X0[8] = {gf0 * x0.x, gf0 * x0.y, gf0 * x0.z, gf0 * x0.w,
                           gf0 * x1.x, gf0 * x1.y, gf0 * x1.z, gf0 * x1.w};
            float agg0 = softagg8(X0);
            float X1[8] = {gf1 * y0.x, gf1 * y0.y, gf1 * y0.z, gf1 * y0.w,
                           gf1 * y1.x, gf1 * y1.y, gf1 * y1.z, gf1 * y1.w};
            float agg1 = softagg8(X1);
            float X2[8] = {gf2 * z0.x, gf2 * z0.y, gf2 * z0.z, gf2 * z0.w,
                           gf2 * z1.x, gf2 * z1.y, gf2 * z1.z, gf2 * z1.w};
            float agg2 = softagg8(X2);

#pragma unroll 8
            for (int j = 0; j < 32; j++) {
                float aj = __shfl_sync(FULL, agg0, j);
                float4 w = *(const float4*)&s_w2[j * 128 + k4];
                acc.x = fmaf(aj, w.x, acc.x); acc.y = fmaf(aj, w.y, acc.y);
                acc.z = fmaf(aj, w.z, acc.z); acc.w = fmaf(aj, w.w, acc.w);
            }
#pragma unroll 8
            for (int j = 0; j < 32; j++) {
                float aj = __shfl_sync(FULL, agg1, j);
                float4 w = *(const float4*)&s_w2[(j + 32) * 128 + k4];
                acc.x = fmaf(aj, w.x, acc.x); acc.y = fmaf(aj, w.y, acc.y);
                acc.z = fmaf(aj, w.z, acc.z); acc.w = fmaf(aj, w.w, acc.w);
            }
#pragma unroll
            for (int j = 0; j < 6; j++) {
                float aj = __shfl_sync(FULL, agg2, j);
                float4 w = *(const float4*)&s_w2[(j + 64) * 128 + k4];
                acc.x = fmaf(aj, w.x, acc.x); acc.y = fmaf(aj, w.y, acc.y);
                acc.z = fmaf(aj, w.z, acc.z); acc.w = fmaf(aj, w.w, acc.w);
            }
            sm0 += acc.x; sq0 += (double)acc.x * acc.x;
            sm1 += acc.y; sq1 += (double)acc.y * acc.y;
            sm2 += acc.z; sq2 += (double)acc.z * acc.z;
            sm3 += acc.w; sq3 += (double)acc.w * acc.w;
        }
        *(float4*)&g_pre2[(size_t)row * 128 + k4] = acc;
    }
    atomicAdd(&ssm[k4 + 0], sm0); atomicAdd(&ssq[k4 + 0], sq0);
    atomicAdd(&ssm[k4 + 1], sm1); atomicAdd(&ssq[k4 + 1], sq1);
    atomicAdd(&ssm[k4 + 2], sm2); atomicAdd(&ssq[k4 + 2], sq2);
    atomicAdd(&ssm[k4 + 3], sm3); atomicAdd(&ssq[k4 + 3], sq3);
    __syncthreads();
    if (tid < 128) {
        atomicAdd(&g_acc2[tid], ssm[tid]);
        atomicAdd(&g_acc2[128 + tid], ssq[tid]);
    }
}

__global__ void k_fin2(const float* __restrict__ g2, const float* __restrict__ bt2,
                       const float* __restrict__ b2_0) {
    int c = threadIdx.x;   // 128
    double M = (double)g_mcnt;
    double bv = (double)b2_0[c];
    double s = g_acc2[c] + M * bv;
    double ss = g_acc2[128 + c] + M * bv * bv;
    double n = 131072.0;
    double mean = s / n;
    double var = ss / n - mean * mean;
    float sc = (float)((double)g2[c] / sqrt(var + 1e-5));
    g_scale2[c] = sc;
    g_shift2[c] = (float)((double)bt2[c] - mean * (double)sc);
}

// ---------------- k_final: wmid@w2_1 + res + gelu + max over NS ----------
__global__ __launch_bounds__(128) void k_final(const float* __restrict__ w2_1,
                                               const float* __restrict__ b2_1,
                                               const float* __restrict__ res_b,
                                               float* __restrict__ out,
                                               int out_size) {
    __shared__ float s_wm[KNS][128];
    __shared__ float s_rs[KNS][128];
    __shared__ float s_red[4][128];
    int q = blockIdx.x, tid = threadIdx.x;
    int b = q >> 10;
    int kg = tid & 31, rg = tid >> 5;
    int k4 = kg * 4;

    for (int t = tid; t < KNS * 128; t += 128) {
        int r = t >> 7, k = t & 127;
        float pre = g_pre2[((size_t)q * KNS + r) * 128 + k];
        s_wm[r][k] = fmaxf(0.f, fmaf(pre, g_scale2[k], g_shift2[k]));
        int id = g_idx[q * KNS + r];
        s_rs[r][k] = (id < 0) ? 0.f : g_res[((size_t)((b << 12) + id)) * 128 + k];
    }
    __syncthreads();

    float acc[8][4];
#pragma unroll
    for (int m = 0; m < 4; m++) {
        float init = b2_1[k4 + m] + res_b[k4 + m];
#pragma unroll
        for (int r = 0; r < 8; r++) acc[r][m] = init;
    }
    for (int j = 0; j < 128; j++) {
        float4 w = *(const float4*)&w2_1[j * 128 + k4];
#pragma unroll
        for (int r = 0; r < 8; r++) {
            float wm = s_wm[rg * 8 + r][j];
            acc[r][0] = fmaf(wm, w.x, acc[r][0]);
            acc[r][1] = fmaf(wm, w.y, acc[r][1]);
            acc[r][2] = fmaf(wm, w.z, acc[r][2]);
            acc[r][3] = fmaf(wm, w.w, acc[r][3]);
        }
    }
#pragma unroll
    for (int m = 0; m < 4; m++) {
        float mxv = -INFINITY;
#pragma unroll
        for (int r = 0; r < 8; r++) {
            float x = acc[r][m] + s_rs[rg * 8 + r][k4 + m];
            float gl = 0.5f * x * (1.f + erff(x * 0.70710678118654752440f));
            mxv = fmaxf(mxv, gl);
        }
        s_red[rg][k4 + m] = mxv;
    }
    __syncthreads();
    {
        float m0 = fmaxf(fmaxf(s_red[0][tid], s_red[1][tid]),
                         fmaxf(s_red[2][tid], s_red[3][tid]));
        out[(size_t)q * 128 + tid] = m0;
    }
    if (tid < 3 && out_size >= NB * NSAMP * 128 + NB * NSAMP * 3) {
        out[(size_t)NB * NSAMP * 128 + q * 3 + tid] = g_newxyz[q * 3 + tid];
    }
}

// ---------------- host launcher ----------------
extern "C" void kernel_launch(void* const* d_in, const int* in_sizes, int n_in,
                              void* d_out, int out_size) {
    const float* xyz   = (const float*)d_in[0];
    const float* f     = (const float*)d_in[1];
    const float* fp    = (const float*)d_in[2];
    const float* w1_0  = (const float*)d_in[3];
    const float* b1_0  = (const float*)d_in[4];
    const float* g1_0  = (const float*)d_in[5];
    const float* bt1_0 = (const float*)d_in[6];
    const float* w1_1  = (const float*)d_in[7];
    const float* b1_1  = (const float*)d_in[8];
    const float* w2_0  = (const float*)d_in[9];
    const float* b2_0  = (const float*)d_in[10];
    const float* g2_0  = (const float*)d_in[11];
    const float* bt2_0 = (const float*)d_in[12];
    const float* w2_1  = (const float*)d_in[13];
    const float* b2_1  = (const float*)d_in[14];
    const float* res_w = (const float*)d_in[15];
    const float* res_b = (const float*)d_in[16];
    float* out = (float*)d_out;
    (void)in_sizes; (void)n_in;

    k_prep<<<1, 256>>>(w1_0, b1_0, fp);
    k_fps<<<NB, 256>>>(xyz);
    k_ball<<<(NB * NSAMP) / 8, 256>>>(xyz);
    k_hist<<<NROWS / 256, 256>>>();
    k_stats1w<<<NPTS / 256, 256>>>(xyz, fp, w1_0);
    k_fin1<<<1, 64>>>(g1_0, bt1_0, fp, w1_0);
    k_pointA<<<NPTS / 8, 256>>>(xyz, fp, w1_0, w1_1, b1_1);
    k_pointres<<<NPTS / 8, 256>>>(f, res_w);
    k_main2<<<NROWS / 128, 256>>>(xyz, f, w2_0, b2_0);
    k_fin2<<<1, 128>>>(g2_0, bt2_0, b2_0);
    k_final<<<NB * NSAMP, 128>>>(w2_1, b2_1, res_b, out, out_size);
}

// round 13
// speedup vs baseline: 1.6551x; 1.2055x over previous
#include <cuda_runtime.h>
#include <math.h>

#define FULL 0xffffffffu

// B=4, N=4096, S=1024, NS=32, V=8, CIN=64, COUT=128, C1=70
#define NB 4
#define NP 4096
#define NSAMP 1024
#define KNS 32
#define NV 8
#define NPTS (NB * NP)            // 16384
#define NROWS (NB * NSAMP * KNS)  // 131072

// ---------------- device scratch (static) ----------------
__device__ float  g_newxyz[NB * NSAMP * 3];
__device__ int    g_idx[NROWS];
__device__ float  g_pre2[(size_t)NROWS * 128];     // 67 MB
__device__ float  g_A[(size_t)NPTS * 70 * 8];      // 36.7 MB  [point][j][v]
__device__ float  g_agg[(size_t)NROWS * 70];       // 36.7 MB  [row][j]
__device__ float  g_res[(size_t)NPTS * 128];       // 8.4 MB
__device__ int    g_cnt[NPTS];
__device__ int    g_mcnt;
__device__ double g_acc1[128];    // [0:64) sum, [64:128) sumsq
__device__ double g_acc2[256];    // [0:128) sum, [128:256) sumsq
__device__ float  g_E[192];
__device__ float  g_Kv[NV * 64];
__device__ float  g_scale1[64], g_shift1[64];
__device__ float  g_scale2[128], g_shift2[128];

// ---------------- k_prep ----------------
__global__ void k_prep(const float* __restrict__ w1_0,
                       const float* __restrict__ b1_0,
                       const float* __restrict__ fp) {
    int t = threadIdx.x;             // 256
    if (t < 128) g_acc1[t] = 0.0;
    g_acc2[t] = 0.0;
    for (int i = t; i < NPTS; i += 256) g_cnt[i] = 0;
    if (t == 0) g_mcnt = 0;
    if (t < 192) {
        int d = t >> 6, c = t & 63;
        g_E[t] = (w1_0[(3 + d) * 64 + c] - w1_0[d * 64 + c]) + w1_0[(7 + d) * 64 + c];
    }
    if (t < 64) {
        for (int v = 0; v < NV; v++) {
            float s = b1_0[t];
            for (int d = 0; d < 3; d++) {
                float wd = w1_0[(3 + d) * 64 + t] - w1_0[d * 64 + t];
                s += fp[v * 3 + d] * (w1_0[(10 + d) * 64 + t] - wd);
            }
            g_Kv[v * 64 + t] = s;
        }
    }
}

// ---------------- k_fps: redux-based argmax, one barrier / iter ----------
__global__ __launch_bounds__(256) void k_fps(const float* __restrict__ xyz) {
    int b = blockIdx.x, tid = threadIdx.x;
    const float* X = xyz + (size_t)b * NP * 3;
    float px[16], py[16], pz[16], mind[16];
#pragma unroll
    for (int i = 0; i < 16; i++) {
        int p = tid + 256 * i;
        px[i] = X[p * 3 + 0];
        py[i] = X[p * 3 + 1];
        pz[i] = X[p * 3 + 2];
        mind[i] = 1e10f;
    }
    __shared__ unsigned long long s_part[2][8];
    float cx = X[0], cy = X[1], cz = X[2];     // point index 0
    if (tid == 0) {
        float* o = g_newxyz + (size_t)b * NSAMP * 3;
        o[0] = cx; o[1] = cy; o[2] = cz;
    }
    int wid = tid >> 5, lane = tid & 31;
    for (int it = 1; it < NSAMP; it++) {
        float v = 0.0f;   // distances are >= 0
#pragma unroll
        for (int i = 0; i < 16; i++) {
            float dx = px[i] - cx, dy = py[i] - cy, dz = pz[i] - cz;
            float d = fmaf(dz, dz, fmaf(dy, dy, dx * dx));
            float m = fminf(mind[i], d);
            mind[i] = m;
            v = fmaxf(v, m);
        }
        // warp max value (positive floats compare as u32)
        unsigned wmax = __reduce_max_sync(FULL, __float_as_uint(v));
        // first local index achieving wmax (descending scan -> smallest i wins)
        unsigned cand = 0xFFFFFFFFu;
#pragma unroll
        for (int i = 15; i >= 0; i--)
            if (__float_as_uint(mind[i]) == wmax) cand = (unsigned)(tid + 256 * i);
        unsigned wp = __reduce_min_sync(FULL, cand);   // min global p among ties
        if (lane == 0)
            s_part[it & 1][wid] =
                ((unsigned long long)wmax << 32) | (unsigned long long)(0xFFFFFFFFu - wp);
        __syncthreads();
        unsigned long long bb = s_part[it & 1][0];
#pragma unroll
        for (int w = 1; w < 8; w++) {
            unsigned long long t = s_part[it & 1][w];
            bb = bb > t ? bb : t;
        }
        int bi = (int)(0xFFFFFFFFu - (unsigned)(bb & 0xFFFFFFFFull));
        cx = X[bi * 3 + 0]; cy = X[bi * 3 + 1]; cz = X[bi * 3 + 2];
        if (tid == 0) {
            float* o = g_newxyz + ((size_t)b * NSAMP + it) * 3;
            o[0] = cx; o[1] = cy; o[2] = cz;
        }
    }
}

// ---------------- k_ball (+fused hist) ----------------
__global__ __launch_bounds__(256) void k_ball(const float* __restrict__ xyz) {
    int q = blockIdx.x * 8 + (threadIdx.x >> 5);
    int lane = threadIdx.x & 31;
    int b = q >> 10;
    const float* X = xyz + (size_t)b * NP * 3;
    float qx = g_newxyz[q * 3 + 0], qy = g_newxyz[q * 3 + 1], qz = g_newxyz[q * 3 + 2];
    const float R2 = (float)(0.2 * 0.2);
    int found = 0;
    unsigned lmask = (1u << lane) - 1u;
    for (int base = 0; base < NP && found < KNS; base += 32) {
        int p = base + lane;
        float dx = X[p * 3 + 0] - qx, dy = X[p * 3 + 1] - qy, dz = X[p * 3 + 2] - qz;
        float d = fmaf(dz, dz, fmaf(dy, dy, dx * dx));
        bool in = d < R2;
        unsigned m = __ballot_sync(FULL, in);
        if (in) {
            int pos = found + __popc(m & lmask);
            if (pos < KNS) {
                g_idx[q * KNS + pos] = p;
                atomicAdd(&g_cnt[(b << 12) + p], 1);
            }
        }
        found += __popc(m);
    }
    if (found > KNS) found = KNS;
    for (int k2 = found + lane; k2 < KNS; k2 += 32) g_idx[q * KNS + k2] = -1;
    if (lane == 0 && found < KNS) atomicAdd(&g_mcnt, KNS - found);
}

// ---------------- k_stats1w: BN1 sums, count-weighted over 16K points ----
__global__ __launch_bounds__(256) void k_stats1w(const float* __restrict__ xyz,
                                                 const float* __restrict__ fp,
                                                 const float* __restrict__ w1_0) {
    __shared__ double ssm[64], ssq[64];
    int tid = threadIdx.x;
    int c = tid & 63, slot = tid >> 6;
    if (tid < 64) { ssm[tid] = 0.0; ssq[tid] = 0.0; }
    __syncthreads();
    float Ex = g_E[c], Ey = g_E[64 + c], Ez = g_E[128 + c];
    float w6 = w1_0[6 * 64 + c];
    float Kv[NV];
#pragma unroll
    for (int v = 0; v < NV; v++) Kv[v] = g_Kv[v * 64 + c];
    float fx[NV], fy[NV], fz[NV];
#pragma unroll
    for (int v = 0; v < NV; v++) { fx[v] = fp[v * 3]; fy[v] = fp[v * 3 + 1]; fz[v] = fp[v * 3 + 2]; }
    double sm = 0.0, sq = 0.0;
    int p0 = blockIdx.x * 256 + slot * 64;    // 64 blocks
    for (int i = 0; i < 64; i++) {
        int p = p0 + i;
        int w = g_cnt[p];
        if (!w) continue;
        float gx = xyz[p * 3], gy = xyz[p * 3 + 1], gz = xyz[p * 3 + 2];
        float base = fmaf(gz, Ez, fmaf(gy, Ey, gx * Ex));
        float lsm = 0.f, lsq = 0.f;
#pragma unroll
        for (int v = 0; v < NV; v++) {
            float ax = gx - fx[v], ay = gy - fy[v], az = gz - fz[v];
            float e = sqrtf(fmaf(az, az, fmaf(ay, ay, ax * ax)));
            float pre = base + fmaf(e, w6, Kv[v]);
            lsm += pre;
            lsq = fmaf(pre, pre, lsq);
        }
        sm += (double)w * lsm;
        sq += (double)w * lsq;
    }
    atomicAdd(&ssm[c], sm);
    atomicAdd(&ssq[c], sq);
    __syncthreads();
    if (tid < 64) {
        atomicAdd(&g_acc1[tid], ssm[tid]);
        atomicAdd(&g_acc1[64 + tid], ssq[tid]);
    }
}

__global__ void k_fin1(const float* __restrict__ g1, const float* __restrict__ bt1,
                       const float* __restrict__ fp, const float* __restrict__ w1_0) {
    int c = threadIdx.x;   // 64
    double M = (double)g_mcnt;       // masked rows (each has 8 v samples)
    double s = g_acc1[c], ss = g_acc1[64 + c];
    float w6 = w1_0[6 * 64 + c];
#pragma unroll
    for (int v = 0; v < NV; v++) {
        float ax = 0.f - fp[v * 3], ay = 0.f - fp[v * 3 + 1], az = 0.f - fp[v * 3 + 2];
        float e = sqrtf(fmaf(az, az, fmaf(ay, ay, ax * ax)));
        float pre = fmaf(e, w6, g_Kv[v * 64 + c]);   // base = 0
        s += M * (double)pre;
        ss += M * (double)pre * pre;
    }
    double n = 1048576.0;
    double mean = s / n;
    double var = ss / n - mean * mean;
    float sc = (float)((double)g1[c] / sqrt(var + 1e-5));
    g_scale1[c] = sc;
    g_shift1[c] = (float)((double)bt1[c] - mean * (double)sc);
}

// ---------------- k_pointA: per-point m1 MLP -> A[point][70][8] ----------
__global__ __launch_bounds__(256) void k_pointA(const float* __restrict__ xyz,
                                                const float* __restrict__ fp,
                                                const float* __restrict__ w1_0,
                                                const float* __restrict__ w1_1,
                                                const float* __restrict__ b1_1) {
    int p = blockIdx.x * 8 + (threadIdx.x >> 5);   // 0..16383
    int lane = threadIdx.x & 31;
    const float* P = xyz + (size_t)p * 3;
    float gx = P[0], gy = P[1], gz = P[2];

    int c0 = lane, c1 = lane + 32;
    float E00 = g_E[c0], E10 = g_E[64 + c0], E20 = g_E[128 + c0];
    float E01 = g_E[c1], E11 = g_E[64 + c1], E21 = g_E[128 + c1];
    float w60 = w1_0[6 * 64 + c0], w61 = w1_0[6 * 64 + c1];
    float sc0 = g_scale1[c0], sh0 = g_shift1[c0];
    float sc1 = g_scale1[c1], sh1 = g_shift1[c1];
    float base0 = fmaf(gz, E20, fmaf(gy, E10, gx * E00));
    float base1 = fmaf(gz, E21, fmaf(gy, E11, gx * E01));
    float h0[NV], h1r[NV];
#pragma unroll
    for (int v = 0; v < NV; v++) {
        float fx = fp[v * 3], fy = fp[v * 3 + 1], fz = fp[v * 3 + 2];
        float ax = gx - fx, ay = gy - fy, az = gz - fz;
        float e = sqrtf(fmaf(az, az, fmaf(ay, ay, ax * ax)));
        float p0 = base0 + fmaf(e, w60, g_Kv[v * 64 + c0]);
        float p1 = base1 + fmaf(e, w61, g_Kv[v * 64 + c1]);
        h0[v] = fmaxf(0.f, fmaf(p0, sc0, sh0));
        h1r[v] = fmaxf(0.f, fmaf(p1, sc1, sh1));
    }

    float A0[NV], A1[NV], A2[NV];
    float bb0 = b1_1[lane], bb1 = b1_1[lane + 32];
    float bb2 = (lane < 6) ? b1_1[64 + lane] : 0.f;
#pragma unroll
    for (int v = 0; v < NV; v++) { A0[v] = bb0; A1[v] = bb1; A2[v] = bb2; }
#pragma unroll 4
    for (int c = 0; c < 32; c++) {
        float wA = w1_1[c * 70 + lane];
        float wB = w1_1[c * 70 + 32 + lane];
        float wC = (lane < 6) ? w1_1[c * 70 + 64 + lane] : 0.f;
#pragma unroll
        for (int v = 0; v < NV; v++) {
            float hv = __shfl_sync(FULL, h0[v], c);
            A0[v] = fmaf(hv, wA, A0[v]);
            A1[v] = fmaf(hv, wB, A1[v]);
            A2[v] = fmaf(hv, wC, A2[v]);
        }
    }
#pragma unroll 4
    for (int c = 0; c < 32; c++) {
        float wA = w1_1[(c + 32) * 70 + lane];
        float wB = w1_1[(c + 32) * 70 + 32 + lane];
        float wC = (lane < 6) ? w1_1[(c + 32) * 70 + 64 + lane] : 0.f;
#pragma unroll
        for (int v = 0; v < NV; v++) {
            float hv = __shfl_sync(FULL, h1r[v], c);
            A0[v] = fmaf(hv, wA, A0[v]);
            A1[v] = fmaf(hv, wB, A1[v]);
            A2[v] = fmaf(hv, wC, A2[v]);
        }
    }

    float* d0 = g_A + ((size_t)p * 70 + lane) * 8;
    *(float4*)d0       = make_float4(A0[0], A0[1], A0[2], A0[3]);
    *(float4*)(d0 + 4) = make_float4(A0[4], A0[5], A0[6], A0[7]);
    float* d1 = g_A + ((size_t)p * 70 + 32 + lane) * 8;
    *(float4*)d1       = make_float4(A1[0], A1[1], A1[2], A1[3]);
    *(float4*)(d1 + 4) = make_float4(A1[4], A1[5], A1[6], A1[7]);
    if (lane < 6) {
        float* d2 = g_A + ((size_t)p * 70 + 64 + lane) * 8;
        *(float4*)d2       = make_float4(A2[0], A2[1], A2[2], A2[3]);
        *(float4*)(d2 + 4) = make_float4(A2[4], A2[5], A2[6], A2[7]);
    }
}

// ---------------- k_pointres: res[point] = f[point] @ res_w -------------
__global__ __launch_bounds__(256) void k_pointres(const float* __restrict__ f,
                                                  const float* __restrict__ res_w) {
    int p = blockIdx.x * 8 + (threadIdx.x >> 5);
    int lane = threadIdx.x & 31;
    int k4 = lane * 4;
    const float* FF = f + (size_t)p * 64;
    float f0 = FF[lane], f1 = FF[lane + 32];
    float4 acc = make_float4(0.f, 0.f, 0.f, 0.f);
#pragma unroll 8
    for (int j = 0; j < 32; j++) {
        float fj = __shfl_sync(FULL, f0, j);
        float4 w = *(const float4*)&res_w[j * 128 + k4];
        acc.x = fmaf(fj, w.x, acc.x); acc.y = fmaf(fj, w.y, acc.y);
        acc.z = fmaf(fj, w.z, acc.z); acc.w = fmaf(fj, w.w, acc.w);
    }
#pragma unroll 8
    for (int j = 0; j < 32; j++) {
        float fj = __shfl_sync(FULL, f1, j);
        float4 w = *(const float4*)&res_w[(j + 32) * 128 + k4];
        acc.x = fmaf(fj, w.x, acc.x); acc.y = fmaf(fj, w.y, acc.y);
        acc.z = fmaf(fj, w.z, acc.z); acc.w = fmaf(fj, w.w, acc.w);
    }
    *(float4*)&g_res[(size_t)p * 128 + k4] = acc;
}

// ---------------- softmax helper ----------------
__device__ __forceinline__ float softagg8(const float x[8]) {
    float mx = x[0];
#pragma unroll
    for (int v = 1; v < NV; v++) mx = fmaxf(mx, x[v]);
    float e[NV], se = 0.f;
#pragma unroll
    for (int v = 0; v < NV; v++) { e[v] = __expf(x[v] - mx); se += e[v]; }
    float inv = 1.0f / se, sp = 0.f;
#pragma unroll
    for (int v = 0; v < NV; v++) sp = fmaf(e[v] * inv, x[v], sp);
    return sp;
}

// ---------------- k_agg: per-row softmax -> agg[row][70] -----------------
__global__ __launch_bounds__(256) void k_agg(const float* __restrict__ xyz,
                                             const float* __restrict__ f) {
    int tid = threadIdx.x, lane = tid & 31, wid = tid >> 5;
    int rbase = (blockIdx.x * 8 + wid) * 16;
    for (int r = 0; r < 16; r++) {
        int row = rbase + r;
        int idx = g_idx[row];
        float* dst = g_agg + (size_t)row * 70;
        if (idx < 0) {
            dst[lane] = 0.f; dst[lane + 32] = 0.f;
            if (lane < 6) dst[lane + 64] = 0.f;
            continue;
        }
        int p = ((row >> 15) << 12) + idx;
        const float* P = xyz + (size_t)p * 3;
        float gx = P[0], gy = P[1], gz = P[2];
        int q = row >> 5;
        float nx = g_newxyz[q * 3], ny = g_newxyz[q * 3 + 1], nz = g_newxyz[q * 3 + 2];
        const float* FF = f + (size_t)p * 64;
        float gf0;
        if (lane >= 6)      gf0 = FF[lane - 6];
        else if (lane == 0) gf0 = gx;
        else if (lane == 1) gf0 = gy;
        else if (lane == 2) gf0 = gz;
        else if (lane == 3) gf0 = gx - nx;
        else if (lane == 4) gf0 = gy - ny;
        else                gf0 = gz - nz;
        float gf1 = FF[lane + 26];
        float gf2 = (lane < 6) ? FF[lane + 58] : 0.f;

        const float* A0p = g_A + ((size_t)p * 70 + lane) * 8;
        const float* A1p = g_A + ((size_t)p * 70 + 32 + lane) * 8;
        float4 x0 = *(const float4*)A0p, x1 = *(const float4*)(A0p + 4);
        float4 y0 = *(const float4*)A1p, y1 = *(const float4*)(A1p + 4);
        float4 z0 = make_float4(0.f, 0.f, 0.f, 0.f), z1 = z0;
        if (lane < 6) {
            const float* A2p = g_A + ((size_t)p * 70 + 64 + lane) * 8;
            z0 = *(const float4*)A2p; z1 = *(const float4*)(A2p + 4);
        }
        float X0[8] = {gf0 * x0.x, gf0 * x0.y, gf0 * x0.z, gf0 * x0.w,
                       gf0 * x1.x, gf0 * x1.y, gf0 * x1.z, gf0 * x1.w};
        float X1[8] = {gf1 * y0.x, gf1 * y0.y, gf1 * y0.z, gf1 * y0.w,
                       gf1 * y1.x, gf1 * y1.y, gf1 * y1.z, gf1 * y1.w};
        float X2[8] = {gf2 * z0.x, gf2 * z0.y, gf2 * z0.z, gf2 * z0.w,
                       gf2 * z1.x, gf2 * z1.y, gf2 * z1.z, gf2 * z1.w};
        dst[lane] = softagg8(X0);
        dst[lane + 32] = softagg8(X1);
        if (lane < 6) dst[lane + 64] = softagg8(X2);
    }
}

// ---------------- k_gemm2: pre2 = agg @ w2_0 + b2_0, BN2 stats -----------
__global__ __launch_bounds__(128) void k_gemm2(const float* __restrict__ w2_0,
                                               const float* __restrict__ b2_0) {
    __shared__ float s_w2[70 * 128];
    __shared__ float s_agg[32 * 70];
    __shared__ float s_s[4][128], s_q[4][128];
    int qb = blockIdx.x;          // 0..4095, 32 rows each
    int tid = threadIdx.x;        // 128
    int kg = tid & 31, rg = tid >> 5;
    int k4 = kg * 4;

    for (int i = tid; i < 70 * 128; i += 128) s_w2[i] = w2_0[i];
    {
        const float* src = g_agg + (size_t)qb * 32 * 70;
        for (int i = tid; i < 32 * 70; i += 128) s_agg[i] = src[i];
    }
    __syncthreads();

    float4 b4 = *(const float4*)&b2_0[k4];
    float acc[8][4];
#pragma unroll
    for (int r = 0; r < 8; r++) {
        acc[r][0] = b4.x; acc[r][1] = b4.y; acc[r][2] = b4.z; acc[r][3] = b4.w;
    }
    for (int j = 0; j < 70; j++) {
        float4 w = *(const float4*)&s_w2[j * 128 + k4];
#pragma unroll
        for (int r = 0; r < 8; r++) {
            float a = s_agg[(rg * 8 + r) * 70 + j];
            acc[r][0] = fmaf(a, w.x, acc[r][0]);
            acc[r][1] = fmaf(a, w.y, acc[r][1]);
            acc[r][2] = fmaf(a, w.z, acc[r][2]);
            acc[r][3] = fmaf(a, w.w, acc[r][3]);
        }
    }
    float sm[4] = {0.f, 0.f, 0.f, 0.f}, sq[4] = {0.f, 0.f, 0.f, 0.f};
#pragma unroll
    for (int r = 0; r < 8; r++) {
        size_t row = (size_t)qb * 32 + rg * 8 + r;
        *(float4*)&g_pre2[row * 128 + k4] =
            make_float4(acc[r][0], acc[r][1], acc[r][2], acc[r][3]);
#pragma unroll
        for (int m = 0; m < 4; m++) {
            sm[m] += acc[r][m];
            sq[m] = fmaf(acc[r][m], acc[r][m], sq[m]);
        }
    }
#pragma unroll
    for (int m = 0; m < 4; m++) { s_s[rg][k4 + m] = sm[m]; s_q[rg][k4 + m] = sq[m]; }
    __syncthreads();
    if (tid < 128) {
        float ts = s_s[0][tid] + s_s[1][tid] + s_s[2][tid] + s_s[3][tid];
        float tq = s_q[0][tid] + s_q[1][tid] + s_q[2][tid] + s_q[3][tid];
        atomicAdd(&g_acc2[tid], (double)ts);
        atomicAdd(&g_acc2[128 + tid], (double)tq);
    }
}

__global__ void k_fin2(const float* __restrict__ g2, const float* __restrict__ bt2) {
    int c = threadIdx.x;   // 128
    double n = 131072.0;
    double mean = g_acc2[c] / n;
    double var = g_acc2[128 + c] / n - mean * mean;
    float sc = (float)((double)g2[c] / sqrt(var + 1e-5));
    g_scale2[c] = sc;
    g_shift2[c] = (float)((double)bt2[c] - mean * (double)sc);
}

// ---------------- k_final: wmid@w2_1 + res + gelu + max over NS ----------
__global__ __launch_bounds__(128) void k_final(const float* __restrict__ w2_1,
                                               const float* __restrict__ b2_1,
                                               const float* __restrict__ res_b,
                                               float* __restrict__ out,
                                               int out_size) {
    __shared__ float s_wm[KNS][128];
    __shared__ float s_rs[KNS][128];
    __shared__ float s_red[4][128];
    int q = blockIdx.x, tid = threadIdx.x;
    int b = q >> 10;
    int kg = tid & 31, rg = tid >> 5;
    int k4 = kg * 4;

    for (int t = tid; t < KNS * 128; t += 128) {
        int r = t >> 7, k = t & 127;
        float pre = g_pre2[((size_t)q * KNS + r) * 128 + k];
        s_wm[r][k] = fmaxf(0.f, fmaf(pre, g_scale2[k], g_shift2[k]));
        int id = g_idx[q * KNS + r];
        s_rs[r][k] = (id < 0) ? 0.f : g_res[((size_t)((b << 12) + id)) * 128 + k];
    }
    __syncthreads();

    float acc[8][4];
#pragma unroll
    for (int m = 0; m < 4; m++) {
        float init = b2_1[k4 + m] + res_b[k4 + m];
#pragma unroll
        for (int r = 0; r < 8; r++) acc[r][m] = init;
    }
    for (int j = 0; j < 128; j++) {
        float4 w = *(const float4*)&w2_1[j * 128 + k4];
#pragma unroll
        for (int r = 0; r < 8; r++) {
            float wm = s_wm[rg * 8 + r][j];
            acc[r][0] = fmaf(wm, w.x, acc[r][0]);
            acc[r][1] = fmaf(wm, w.y, acc[r][1]);
            acc[r][2] = fmaf(wm, w.z, acc[r][2]);
            acc[r][3] = fmaf(wm, w.w, acc[r][3]);
        }
    }
#pragma unroll
    for (int m = 0; m < 4; m++) {
        float mxv = -INFINITY;
#pragma unroll
        for (int r = 0; r < 8; r++) {
            float x = acc[r][m] + s_rs[rg * 8 + r][k4 + m];
            float gl = 0.5f * x * (1.f + erff(x * 0.70710678118654752440f));
            mxv = fmaxf(mxv, gl);
        }
        s_red[rg][k4 + m] = mxv;
    }
    __syncthreads();
    {
        float m0 = fmaxf(fmaxf(s_red[0][tid], s_red[1][tid]),
                         fmaxf(s_red[2][tid], s_red[3][tid]));
        out[(size_t)q * 128 + tid] = m0;
    }
    if (tid < 3 && out_size >= NB * NSAMP * 128 + NB * NSAMP * 3) {
        out[(size_t)NB * NSAMP * 128 + q * 3 + tid] = g_newxyz[q * 3 + tid];
    }
}

// ---------------- host launcher ----------------
extern "C" void kernel_launch(void* const* d_in, const int* in_sizes, int n_in,
                              void* d_out, int out_size) {
    const float* xyz   = (const float*)d_in[0];
    const float* f     = (const float*)d_in[1];
    const float* fp    = (const float*)d_in[2];
    const float* w1_0  = (const float*)d_in[3];
    const float* b1_0  = (const float*)d_in[4];
    const float* g1_0  = (const float*)d_in[5];
    const float* bt1_0 = (const float*)d_in[6];
    const float* w1_1  = (const float*)d_in[7];
    const float* b1_1  = (const float*)d_in[8];
    const float* w2_0  = (const float*)d_in[9];
    const float* b2_0  = (const float*)d_in[10];
    const float* g2_0  = (const float*)d_in[11];
    const float* bt2_0 = (const float*)d_in[12];
    const float* w2_1  = (const float*)d_in[13];
    const float* b2_1  = (const float*)d_in[14];
    const float* res_w = (const float*)d_in[15];
    const float* res_b = (const float*)d_in[16];
    float* out = (float*)d_out;
    (void)in_sizes; (void)n_in;

    k_prep<<<1, 256>>>(w1_0, b1_0, fp);
    k_fps<<<NB, 256>>>(xyz);
    k_ball<<<(NB * NSAMP) / 8, 256>>>(xyz);
    k_stats1w<<<NPTS / 256, 256>>>(xyz, fp, w1_0);
    k_fin1<<<1, 64>>>(g1_0, bt1_0, fp, w1_0);
    k_pointA<<<NPTS / 8, 256>>>(xyz, fp, w1_0, w1_1, b1_1);
    k_pointres<<<NPTS / 8, 256>>>(f, res_w);
    k_agg<<<NROWS / 128, 256>>>(xyz, f);
    k_gemm2<<<NROWS / 32, 128>>>(w2_0, b2_0);
    k_fin2<<<1, 128>>>(g2_0, bt2_0);
    k_final<<<NB * NSAMP, 128>>>(w2_1, b2_1, res_b, out, out_size);
}